// round 1
// baseline (speedup 1.0000x reference)
#include <cuda_runtime.h>
#include <cstdint>

#define Hh 576
#define Ww 640
#define HW (Hh*Ww)
#define NPTS_MAX 200000
#define BIGF 1e10f
#define EPSF 1e-5f

// ---- scratch (__device__ globals: no allocation allowed) ----
__device__ unsigned int g_depth_u[HW];   // z-buffer as uint bits (z>0 -> monotone)
__device__ float        g_rowmin[HW];    // separable 5-wide row min
__device__ float        g_patchmin[HW];  // 5x5 patch min
__device__ float4       g_acc4[HW];      // color.xyz + imweights accumulator

__device__ __forceinline__ void red_add_v4(float4* p, float a, float b, float c, float d) {
    asm volatile("red.global.add.v4.f32 [%0], {%1,%2,%3,%4};"
                 :: "l"(__cvta_generic_to_global(p)),
                    "f"(a), "f"(b), "f"(c), "f"(d) : "memory");
}
__device__ __forceinline__ void red_add_f32(float* p, float v) {
    asm volatile("red.global.add.f32 [%0], %1;"
                 :: "l"(__cvta_generic_to_global(p)), "f"(v) : "memory");
}

// ---- k0: init scratch + zero accumulated output regions ----
__global__ void k_init(float* __restrict__ out_weight) {
    int i = blockIdx.x * blockDim.x + threadIdx.x;
    if (i >= HW) return;
    g_depth_u[i] = __float_as_uint(BIGF);
    g_acc4[i] = make_float4(0.f, 0.f, 0.f, 0.f);
    out_weight[i] = 0.f;
}

// ---- k1: z-buffer scatter-min ----
__global__ void k_zmin(const float* __restrict__ pts, const int* __restrict__ mask, int n) {
    int i = blockIdx.x * blockDim.x + threadIdx.x;
    if (i >= n) return;
    float x = pts[3*i], y = pts[3*i+1], z = pts[3*i+2];
    int px = (int)floorf(x), py = (int)floorf(y);
    bool valid = (px >= 0) & (px < Ww) & (py >= 0) & (py < Hh) & (mask[i] > 0);
    if (valid)
        atomicMin(&g_depth_u[py * Ww + px], __float_as_uint(z));
}

// ---- k2: row min (width 5, SAME pad with BIG) ----
__global__ void k_rowmin() {
    int i = blockIdx.x * blockDim.x + threadIdx.x;
    if (i >= HW) return;
    int r = i / Ww, c = i % Ww;
    float m = BIGF;
    #pragma unroll
    for (int d = -2; d <= 2; ++d) {
        int cc = c + d;
        if (cc >= 0 && cc < Ww)
            m = fminf(m, __uint_as_float(g_depth_u[r * Ww + cc]));
    }
    g_rowmin[i] = m;
}

// ---- k3: col min (height 5) ----
__global__ void k_colmin() {
    int i = blockIdx.x * blockDim.x + threadIdx.x;
    if (i >= HW) return;
    int r = i / Ww, c = i % Ww;
    float m = BIGF;
    #pragma unroll
    for (int d = -2; d <= 2; ++d) {
        int rr = r + d;
        if (rr >= 0 && rr < Hh)
            m = fminf(m, g_rowmin[rr * Ww + c]);
    }
    g_patchmin[i] = m;
}

// ---- k4: visibility + 7x7 splat ----
__global__ void k_splat(const float* __restrict__ pts,
                        const float* __restrict__ color,
                        const float* __restrict__ imw,
                        const int*   __restrict__ mask,
                        const float* __restrict__ thresh,
                        float* __restrict__ out_weight,
                        float* __restrict__ out_vis,
                        int n) {
    int i = blockIdx.x * blockDim.x + threadIdx.x;
    if (i >= n) return;
    float x = pts[3*i], y = pts[3*i+1], z = pts[3*i+2];
    int px = (int)floorf(x), py = (int)floorf(y);
    bool valid = (px >= 0) & (px < Ww) & (py >= 0) & (py < Hh) & (mask[i] > 0);
    int cx = min(max(px, 0), Ww - 1);
    int cy = min(max(py, 0), Hh - 1);
    float pm = g_patchmin[cy * Ww + cx];
    float th = thresh[0];
    bool vis = valid && (z <= pm + th);
    out_vis[i] = vis ? 1.0f : 0.0f;
    if (!vis) return;

    float c0 = color[3*i], c1 = color[3*i+1], c2 = color[3*i+2];
    float iw = imw[i];

    #pragma unroll
    for (int oy = -3; oy <= 3; ++oy) {
        int sy = py + oy;
        if (sy < 0 || sy >= Hh) continue;
        float dy = (float)sy + 0.5f - y;
        #pragma unroll
        for (int ox = -3; ox <= 3; ++ox) {
            int sx = px + ox;
            if (sx < 0 || sx >= Ww) continue;
            float dx = (float)sx + 0.5f - x;
            float w = 1.0f / (dx * dx + dy * dy + EPSF);
            int idx = sy * Ww + sx;
            red_add_v4(&g_acc4[idx], w * c0, w * c1, w * c2, w * iw);
            red_add_f32(&out_weight[idx], w);
        }
    }
}

// ---- k5: finalize depth + scatter color/imweights to output layout ----
__global__ void k_final(float* __restrict__ out_depth,
                        float* __restrict__ out_color,
                        float* __restrict__ out_imw) {
    int i = blockIdx.x * blockDim.x + threadIdx.x;
    if (i >= HW) return;
    float d = __uint_as_float(g_depth_u[i]);
    out_depth[i] = (d >= BIGF) ? 0.0f : d;
    float4 a = g_acc4[i];
    out_color[3*i]   = a.x;
    out_color[3*i+1] = a.y;
    out_color[3*i+2] = a.z;
    out_imw[i] = a.w;
}

extern "C" void kernel_launch(void* const* d_in, const int* in_sizes, int n_in,
                              void* d_out, int out_size) {
    const float* pts    = (const float*)d_in[0];   // [1,N,3]
    const float* color  = (const float*)d_in[1];   // [1,N,3]
    const float* imw    = (const float*)d_in[2];   // [1,N,1]
    const int*   mask   = (const int*)  d_in[3];   // [1,N]
    const float* thresh = (const float*)d_in[4];   // [1]
    int n = in_sizes[3];                           // N = 200000

    float* out = (float*)d_out;
    float* out_depth  = out;            // [H,W]
    float* out_color  = out + HW;       // [H,W,3]
    float* out_imw    = out + HW * 4;   // [H,W,1]
    float* out_weight = out + HW * 5;   // [H,W]
    float* out_vis    = out + HW * 6;   // [N]

    const int BT = 256;
    int gp = (n + BT - 1) / BT;
    int gi = (HW + BT - 1) / BT;

    k_init<<<gi, BT>>>(out_weight);
    k_zmin<<<gp, BT>>>(pts, mask, n);
    k_rowmin<<<gi, BT>>>();
    k_colmin<<<gi, BT>>>();
    k_splat<<<gp, BT>>>(pts, color, imw, mask, thresh, out_weight, out_vis, n);
    k_final<<<gi, BT>>>(out_depth, out_color, out_imw);
}